// round 1
// baseline (speedup 1.0000x reference)
#include <cuda_runtime.h>
#include <cstddef>

#define N_NODES 100000
#define N_EDGES 640000
#define DIM 128
#define ALPHA 0.3f

// Degree accumulator (allocation-free scratch per harness rules).
__device__ float g_deg[N_NODES];

__global__ void zero_deg_kernel() {
    int i = blockIdx.x * blockDim.x + threadIdx.x;
    if (i < N_NODES) g_deg[i] = 0.0f;
}

// One warp per edge. 32 lanes x float4 = 128 floats = one embedding row.
__global__ void edge_scatter_kernel(const float* __restrict__ src_emb,
                                    const float* __restrict__ edge_emb,
                                    const int*   __restrict__ src_idx,
                                    const int*   __restrict__ dst_idx,
                                    float*       __restrict__ out_sum) {
    int g    = blockIdx.x * blockDim.x + threadIdx.x;
    int e    = g >> 5;
    int lane = g & 31;
    if (e >= N_EDGES) return;

    int s = src_idx[e];   // broadcast load within warp
    int d = dst_idx[e];

    const float4 a = *reinterpret_cast<const float4*>(src_emb  + (size_t)s * DIM + lane * 4);
    const float4 b = *reinterpret_cast<const float4*>(edge_emb + (size_t)e * DIM + lane * 4);
    float4 m;
    m.x = a.x + b.x; m.y = a.y + b.y; m.z = a.z + b.z; m.w = a.w + b.w;

    float* p = out_sum + (size_t)d * DIM + lane * 4;
    // Vector global reduction (sm_90+): one REDG for 16 bytes instead of 4 scalar atomics.
    asm volatile("red.global.add.v4.f32 [%0], {%1, %2, %3, %4};"
                 :: "l"(p), "f"(m.x), "f"(m.y), "f"(m.z), "f"(m.w) : "memory");

    if (lane == 0) atomicAdd(&g_deg[d], 1.0f);
}

// One warp per node: mean + lerp + zero-for-isolated, in place over out_sum.
__global__ void finalize_kernel(const float* __restrict__ dst_emb,
                                float*       __restrict__ out) {
    int g    = blockIdx.x * blockDim.x + threadIdx.x;
    int n    = g >> 5;
    int lane = g & 31;
    if (n >= N_NODES) return;

    float deg = g_deg[n];
    size_t off = (size_t)n * DIM + lane * 4;
    float4 s  = *reinterpret_cast<const float4*>(out + off);
    float4 de = *reinterpret_cast<const float4*>(dst_emb + off);

    float4 r;
    if (deg > 0.0f) {
        float inv = (1.0f - ALPHA) / deg;   // deg >= 1 here, so max(deg,1)=deg
        r.x = ALPHA * de.x + s.x * inv;
        r.y = ALPHA * de.y + s.y * inv;
        r.z = ALPHA * de.z + s.z * inv;
        r.w = ALPHA * de.w + s.w * inv;
    } else {
        r.x = r.y = r.z = r.w = 0.0f;
    }
    *reinterpret_cast<float4*>(out + off) = r;
}

extern "C" void kernel_launch(void* const* d_in, const int* in_sizes, int n_in,
                              void* d_out, int out_size) {
    const float* src_emb  = (const float*)d_in[0];
    const float* dst_emb  = (const float*)d_in[1];
    const float* edge_emb = (const float*)d_in[2];
    const int*   src_idx  = (const int*)d_in[3];
    const int*   dst_idx  = (const int*)d_in[4];
    float* out = (float*)d_out;

    // Zero the accumulation buffer (d_out doubles as scratch for segment sums).
    cudaMemsetAsync(out, 0, (size_t)N_NODES * DIM * sizeof(float));
    zero_deg_kernel<<<(N_NODES + 255) / 256, 256>>>();

    {
        long long total = (long long)N_EDGES * 32;
        int threads = 256;
        int blocks = (int)((total + threads - 1) / threads);
        edge_scatter_kernel<<<blocks, threads>>>(src_emb, edge_emb, src_idx, dst_idx, out);
    }
    {
        long long total = (long long)N_NODES * 32;
        int threads = 256;
        int blocks = (int)((total + threads - 1) / threads);
        finalize_kernel<<<blocks, threads>>>(dst_emb, out);
    }
}

// round 4
// speedup vs baseline: 1.3269x; 1.3269x over previous
#include <cuda_runtime.h>
#include <cstddef>

#define N_NODES 100000
#define N_EDGES 640000
#define DIM 128
#define ALPHA 0.3f

// Degree accumulator (allocation-free scratch per harness rules).
__device__ float g_deg[N_NODES];

// Zero both the output accumulator (12.8M floats) and g_deg (100k floats)
// in one vectorized kernel: 3,200,000 + 25,000 float4 stores.
#define OUT4 (N_NODES * DIM / 4)
#define DEG4 (N_NODES / 4)

__global__ void init_kernel(float4* __restrict__ out4) {
    int i = blockIdx.x * blockDim.x + threadIdx.x;
    float4 z = make_float4(0.f, 0.f, 0.f, 0.f);
    if (i < OUT4) {
        out4[i] = z;
    } else {
        int j = i - OUT4;
        if (j < DEG4) reinterpret_cast<float4*>(g_deg)[j] = z;
    }
}

__device__ __forceinline__ void redg_v4(float* p, float4 m) {
    asm volatile("red.global.add.v4.f32 [%0], {%1, %2, %3, %4};"
                 :: "l"(p), "f"(m.x), "f"(m.y), "f"(m.z), "f"(m.w) : "memory");
}

// Two edges per warp: 4 independent 128-bit loads in flight before the first
// REDG (the asm memory clobber blocks hoisting past it, so front-load MLP).
// edge_emb is a pure stream -> __ldcs (evict-first) so the 327MB stream does
// not evict the L2-resident src_emb table + accumulator (~108MB working set).
__global__ void edge_scatter_kernel(const float* __restrict__ src_emb,
                                    const float* __restrict__ edge_emb,
                                    const int*   __restrict__ src_idx,
                                    const int*   __restrict__ dst_idx,
                                    float*       __restrict__ out_sum) {
    int g    = blockIdx.x * blockDim.x + threadIdx.x;
    int warp = g >> 5;
    int lane = g & 31;
    int e0 = warp * 2;
    if (e0 >= N_EDGES) return;
    int e1 = e0 + 1;   // N_EDGES is even -> e1 always valid when e0 is

    int s0 = __ldg(src_idx + e0);
    int d0 = __ldg(dst_idx + e0);
    int s1 = __ldg(src_idx + e1);
    int d1 = __ldg(dst_idx + e1);

    const float4* a0p = reinterpret_cast<const float4*>(src_emb  + (size_t)s0 * DIM) + lane;
    const float4* b0p = reinterpret_cast<const float4*>(edge_emb + (size_t)e0 * DIM) + lane;
    const float4* a1p = reinterpret_cast<const float4*>(src_emb  + (size_t)s1 * DIM) + lane;
    const float4* b1p = reinterpret_cast<const float4*>(edge_emb + (size_t)e1 * DIM) + lane;

    float4 a0 = __ldg(a0p);
    float4 b0 = __ldcs(b0p);
    float4 a1 = __ldg(a1p);
    float4 b1 = __ldcs(b1p);

    float4 m0, m1;
    m0.x = a0.x + b0.x; m0.y = a0.y + b0.y; m0.z = a0.z + b0.z; m0.w = a0.w + b0.w;
    m1.x = a1.x + b1.x; m1.y = a1.y + b1.y; m1.z = a1.z + b1.z; m1.w = a1.w + b1.w;

    redg_v4(out_sum + (size_t)d0 * DIM + lane * 4, m0);
    redg_v4(out_sum + (size_t)d1 * DIM + lane * 4, m1);

    if (lane == 0) {
        atomicAdd(&g_deg[d0], 1.0f);
        atomicAdd(&g_deg[d1], 1.0f);
    }
}

// One warp per node: mean + lerp + zero-for-isolated, in place over out_sum.
__global__ void finalize_kernel(const float* __restrict__ dst_emb,
                                float*       __restrict__ out) {
    int g    = blockIdx.x * blockDim.x + threadIdx.x;
    int n    = g >> 5;
    int lane = g & 31;
    if (n >= N_NODES) return;

    float deg = __ldg(&g_deg[n]);
    size_t off = (size_t)n * DIM + (size_t)lane * 4;
    float4 s  = *reinterpret_cast<const float4*>(out + off);
    float4 de = __ldcs(reinterpret_cast<const float4*>(dst_emb + off));

    float4 r;
    if (deg > 0.0f) {
        float inv = (1.0f - ALPHA) / deg;   // deg >= 1 here, so max(deg,1)=deg
        r.x = ALPHA * de.x + s.x * inv;
        r.y = ALPHA * de.y + s.y * inv;
        r.z = ALPHA * de.z + s.z * inv;
        r.w = ALPHA * de.w + s.w * inv;
    } else {
        r.x = r.y = r.z = r.w = 0.0f;
    }
    *reinterpret_cast<float4*>(out + off) = r;
}

extern "C" void kernel_launch(void* const* d_in, const int* in_sizes, int n_in,
                              void* d_out, int out_size) {
    const float* src_emb  = (const float*)d_in[0];
    const float* dst_emb  = (const float*)d_in[1];
    const float* edge_emb = (const float*)d_in[2];
    const int*   src_idx  = (const int*)d_in[3];
    const int*   dst_idx  = (const int*)d_in[4];
    float* out = (float*)d_out;

    {
        int total = OUT4 + DEG4;            // 3,225,000 float4 stores
        int threads = 256;
        int blocks = (total + threads - 1) / threads;
        init_kernel<<<blocks, threads>>>(reinterpret_cast<float4*>(out));
    }
    {
        // one warp per 2 edges
        long long total = (long long)(N_EDGES / 2) * 32;
        int threads = 256;
        int blocks = (int)((total + threads - 1) / threads);
        edge_scatter_kernel<<<blocks, threads>>>(src_emb, edge_emb, src_idx, dst_idx, out);
    }
    {
        long long total = (long long)N_NODES * 32;
        int threads = 256;
        int blocks = (int)((total + threads - 1) / threads);
        finalize_kernel<<<blocks, threads>>>(dst_emb, out);
    }
}